// round 9
// baseline (speedup 1.0000x reference)
#include <cuda_runtime.h>
#include <cstdint>

// Problem constants
#define NN 50000      // nodes
#define NE 500000     // edges
#define DN 128        // node feat
#define DE 128        // edge feat
#define DH 512        // hidden
#define DO 128        // out

// Scratch: P[node][0:512]   = x @ W1[0:128,:]   + b1
//          P[node][512:1024] = x @ W1[128:256,:]
__device__ float g_P[(size_t)NN * 1024];

// ---------------- packed fp32x2 helpers (PTX ISA 8.7, sm_100+) ----------------
__device__ __forceinline__ unsigned long long pack2(float lo, float hi) {
    unsigned long long r;
    asm("mov.b64 %0, {%1, %2};" : "=l"(r) : "f"(lo), "f"(hi));
    return r;
}
__device__ __forceinline__ unsigned long long bcast2(float v) {
    unsigned long long r;
    asm("mov.b64 %0, {%1, %1};" : "=l"(r) : "f"(v));
    return r;
}
__device__ __forceinline__ void unpack2(unsigned long long v, float& lo, float& hi) {
    asm("mov.b64 {%0, %1}, %2;" : "=f"(lo), "=f"(hi) : "l"(v));
}
__device__ __forceinline__ void fma2(unsigned long long& acc, unsigned long long a,
                                     unsigned long long b) {
    asm("fma.rn.f32x2 %0, %1, %2, %0;" : "+l"(acc) : "l"(a), "l"(b));
}
__device__ __forceinline__ unsigned long long add2(unsigned long long a, unsigned long long b) {
    unsigned long long r;
    asm("add.rn.f32x2 %0, %1, %2;" : "=l"(r) : "l"(a), "l"(b));
    return r;
}

// ---------------- shared micro-kernel ----------------
// 8 rows (fixed per warp -> smem broadcast a-loads) x 4 cols (lane*4) x K=128.
// acc[r][0] = packed cols (c0,c0+1), acc[r][1] = packed cols (c0+2,c0+3).
__device__ __forceinline__ void gemm8x4(const float* __restrict__ sA,  // rows base, stride 128
                                        const float* __restrict__ sW,  // [128][128]
                                        int lane, unsigned long long acc[8][2]) {
    const float* wbase = sW + lane * 4;
#pragma unroll 2
    for (int k = 0; k < 128; k += 4) {
        float4 a4[8];
#pragma unroll
        for (int r = 0; r < 8; r++)
            a4[r] = *reinterpret_cast<const float4*>(sA + r * 128 + k);
#pragma unroll
        for (int kk = 0; kk < 4; kk++) {
            ulonglong2 w = *reinterpret_cast<const ulonglong2*>(wbase + (k + kk) * 128);
#pragma unroll
            for (int r = 0; r < 8; r++) {
                float a = (kk == 0) ? a4[r].x : (kk == 1) ? a4[r].y : (kk == 2) ? a4[r].z : a4[r].w;
                unsigned long long a2 = bcast2(a);
                fma2(acc[r][0], a2, w.x);
                fma2(acc[r][1], a2, w.y);
            }
        }
    }
}

// ---------------- Kernel A: node precompute ----------------
// P = x @ [W1a | W1b], b1 folded into first 512 columns.
// Block: 64 nodes x 128 output cols, K = 128 (full depth, single stage).
#define A_SMEM_FLOATS (64 * 128 + 128 * 128)
__global__ __launch_bounds__(256, 1) void node_kernel(const float* __restrict__ x,
                                                      const float* __restrict__ W1,
                                                      const float* __restrict__ b1) {
    extern __shared__ float sm[];
    float* sX = sm;              // [64][128]
    float* sW = sm + 64 * 128;   // [128][128]

    const int n0 = blockIdx.x * 64;
    const int c0 = blockIdx.y * 128;   // over 1024 combined cols
    const int tid = threadIdx.x, warp = tid >> 5, lane = tid & 31;

    // stage x tile
#pragma unroll
    for (int i = 0; i < 8; i++) {
        int idx = tid + i * 256;           // 2048 float4
        int r = idx >> 5, c4 = (idx & 31) * 4;
        int n = n0 + r;
        float4 v = make_float4(0.f, 0.f, 0.f, 0.f);
        if (n < NN) v = *reinterpret_cast<const float4*>(x + (size_t)n * DN + c4);
        *reinterpret_cast<float4*>(sX + r * 128 + c4) = v;
    }
    // stage W tile: cols<512 from W1 rows [0,128), cols>=512 from rows [128,256)
    const int krow0 = (c0 < 512) ? 0 : 128;
    const int wc0 = (c0 < 512) ? c0 : (c0 - 512);
#pragma unroll
    for (int i = 0; i < 16; i++) {
        int idx = tid + i * 256;           // 4096 float4
        int k = idx >> 5, j4 = (idx & 31) * 4;
        *reinterpret_cast<float4*>(sW + k * 128 + j4) =
            *reinterpret_cast<const float4*>(W1 + (size_t)(krow0 + k) * DH + wc0 + j4);
    }
    __syncthreads();

    unsigned long long acc[8][2];
    unsigned long long i0 = 0ull, i1 = 0ull;
    if (c0 < 512) {   // fold b1 into Pa half
        float4 b = *reinterpret_cast<const float4*>(b1 + c0 + lane * 4);
        i0 = pack2(b.x, b.y);
        i1 = pack2(b.z, b.w);
    }
#pragma unroll
    for (int r = 0; r < 8; r++) { acc[r][0] = i0; acc[r][1] = i1; }

    gemm8x4(sX + warp * 8 * 128, sW, lane, acc);

    const int r0 = warp * 8;
#pragma unroll
    for (int r = 0; r < 8; r++) {
        int n = n0 + r0 + r;
        if (n < NN) {
            float f0, f1, f2, f3;
            unpack2(acc[r][0], f0, f1);
            unpack2(acc[r][1], f2, f3);
            *reinterpret_cast<float4*>(g_P + (size_t)n * 1024 + c0 + lane * 4) =
                make_float4(f0, f1, f2, f3);
        }
    }
}

// ---------------- Kernel B: fused edge MLP ----------------
// Block = 64 edges, 256 threads. Hidden dim in 4 chunks of 128.
// Per chunk: H = relu(P_a[row] + P_b[col] + EA @ W1c_chunk)  -> sH
//            Yacc += sH @ W2_chunk  (Yacc persistent in registers)
#define B_SMEM_BYTES ((64 * 128 + 128 * 128 + 64 * 128 + 128 * 128) * 4 + 128 * 4)
__global__ __launch_bounds__(256, 1) void edge_kernel(const float* __restrict__ ea,
                                                      const int* __restrict__ eidx,
                                                      const float* __restrict__ W1,
                                                      const float* __restrict__ W2,
                                                      const float* __restrict__ b2,
                                                      float* __restrict__ out) {
    extern __shared__ float sm[];
    float* sEA = sm;                       // [64][128]
    float* sW1 = sm + 8192;                // [128][128]  (W1c chunk)
    float* sH  = sm + 8192 + 16384;        // [64][128]
    float* sW2 = sm + 8192 + 16384 + 8192; // [128][128]  (W2 chunk)
    int* sIdx = (int*)(sm + 49152);        // [0:64) row idx, [64:128) col idx

    const int e0 = blockIdx.x * 64;
    const int tid = threadIdx.x, warp = tid >> 5, lane = tid & 31;

    if (tid < 128) {
        int e = e0 + (tid & 63);
        int which = tid >> 6;              // 0 = row (source), 1 = col (target)
        int v = 0;
        if (e < NE) v = eidx[(size_t)which * NE + e];
        sIdx[tid] = v;
    }
    // stage edge_attr tile
#pragma unroll
    for (int i = 0; i < 8; i++) {
        int idx = tid + i * 256;
        int r = idx >> 5, c4 = (idx & 31) * 4;
        int e = e0 + r;
        float4 v = make_float4(0.f, 0.f, 0.f, 0.f);
        if (e < NE) v = *reinterpret_cast<const float4*>(ea + (size_t)e * DE + c4);
        *reinterpret_cast<float4*>(sEA + r * 128 + c4) = v;
    }
    __syncthreads();

    // persistent output accumulators: 8 edges x 4 out-cols, init with b2
    unsigned long long yacc[8][2];
    {
        float4 b = *reinterpret_cast<const float4*>(b2 + lane * 4);
        unsigned long long i0 = pack2(b.x, b.y), i1 = pack2(b.z, b.w);
#pragma unroll
        for (int r = 0; r < 8; r++) { yacc[r][0] = i0; yacc[r][1] = i1; }
    }
    const int r0 = warp * 8;

    // hoist gather base pointers out of the chunk loop (indices are loop-invariant)
    const float* pa_base[8];
    const float* pb_base[8];
#pragma unroll
    for (int r = 0; r < 8; r++) {
        int er = r0 + r;
        pa_base[r] = g_P + (size_t)sIdx[er] * 1024 + lane * 4;
        pb_base[r] = g_P + (size_t)sIdx[64 + er] * 1024 + 512 + lane * 4;
    }

    for (int c = 0; c < 4; c++) {
        if (c > 0) __syncthreads();   // prior phase-d must drain before restaging

        // stage W1c chunk (W1 rows 256..383, col block c) and W2 chunk (row block c)
#pragma unroll
        for (int i = 0; i < 16; i++) {
            int idx = tid + i * 256;
            int k = idx >> 5, j4 = (idx & 31) * 4;
            *reinterpret_cast<float4*>(sW1 + k * 128 + j4) =
                *reinterpret_cast<const float4*>(W1 + (size_t)(256 + k) * DH + c * 128 + j4);
            *reinterpret_cast<float4*>(sW2 + k * 128 + j4) =
                *reinterpret_cast<const float4*>(W2 + (size_t)(c * 128 + k) * DO + j4);
        }

        // gather precomputed node terms (global; latency overlapped with staging)
        unsigned long long hacc[8][2];
#pragma unroll
        for (int r = 0; r < 8; r++) {
            ulonglong2 va = *reinterpret_cast<const ulonglong2*>(pa_base[r] + c * 128);
            ulonglong2 vb = *reinterpret_cast<const ulonglong2*>(pb_base[r] + c * 128);
            hacc[r][0] = add2(va.x, vb.x);   // b1 already folded into Pa
            hacc[r][1] = add2(va.y, vb.y);
        }
        __syncthreads();

        // hacc += EA @ W1c_chunk
        gemm8x4(sEA + r0 * 128, sW1, lane, hacc);

        // relu -> sH
#pragma unroll
        for (int r = 0; r < 8; r++) {
            float f0, f1, f2, f3;
            unpack2(hacc[r][0], f0, f1);
            unpack2(hacc[r][1], f2, f3);
            f0 = fmaxf(f0, 0.f); f1 = fmaxf(f1, 0.f);
            f2 = fmaxf(f2, 0.f); f3 = fmaxf(f3, 0.f);
            *reinterpret_cast<float4*>(sH + (r0 + r) * 128 + lane * 4) =
                make_float4(f0, f1, f2, f3);
        }
        __syncthreads();

        // yacc += sH @ W2_chunk
        gemm8x4(sH + r0 * 128, sW2, lane, yacc);
    }

    // write output
#pragma unroll
    for (int r = 0; r < 8; r++) {
        int e = e0 + r0 + r;
        if (e < NE) {
            float f0, f1, f2, f3;
            unpack2(yacc[r][0], f0, f1);
            unpack2(yacc[r][1], f2, f3);
            *reinterpret_cast<float4*>(out + (size_t)e * DO + lane * 4) =
                make_float4(f0, f1, f2, f3);
        }
    }
}

extern "C" void kernel_launch(void* const* d_in, const int* in_sizes, int n_in,
                              void* d_out, int out_size) {
    const float* x    = (const float*)d_in[0];
    const int*   eidx = (const int*)d_in[1];
    const float* ea   = (const float*)d_in[2];
    const float* W1   = (const float*)d_in[3];
    const float* b1   = (const float*)d_in[4];
    const float* W2   = (const float*)d_in[5];
    const float* b2   = (const float*)d_in[6];
    float* out = (float*)d_out;

    const int a_smem = A_SMEM_FLOATS * 4;          // 96 KB
    const int b_smem = B_SMEM_BYTES;               // ~192.5 KB

    static bool attr_done = false;                 // host-side; idempotent driver setup
    if (!attr_done) {
        cudaFuncSetAttribute(node_kernel, cudaFuncAttributeMaxDynamicSharedMemorySize, a_smem);
        cudaFuncSetAttribute(edge_kernel, cudaFuncAttributeMaxDynamicSharedMemorySize, b_smem);
        cudaFuncSetAttribute(node_kernel, cudaFuncAttributePreferredSharedMemoryCarveout,
                             cudaSharedmemCarveoutMaxShared);
        cudaFuncSetAttribute(edge_kernel, cudaFuncAttributePreferredSharedMemoryCarveout,
                             cudaSharedmemCarveoutMaxShared);
        attr_done = true;
    }

    dim3 gridA((NN + 63) / 64, 1024 / 128);        // 782 x 8
    node_kernel<<<gridA, 256, a_smem>>>(x, W1, b1);

    int gridB = (NE + 63) / 64;                    // 7813
    edge_kernel<<<gridB, 256, b_smem>>>(ea, eidx, W1, W2, b2, out);
}

// round 13
// speedup vs baseline: 1.0250x; 1.0250x over previous
#include <cuda_runtime.h>
#include <cstdint>

// Problem constants
#define NN 50000      // nodes
#define NE 500000     // edges
#define DN 128        // node feat
#define DE 128        // edge feat
#define DH 512        // hidden
#define DO 128        // out

// Scratch: P[node][0:512]   = x @ W1[0:128,:]   + b1
//          P[node][512:1024] = x @ W1[128:256,:]
__device__ float g_P[(size_t)NN * 1024];

// ---------------- packed fp32x2 helpers (PTX ISA 8.7, sm_100+) ----------------
__device__ __forceinline__ unsigned long long pack2(float lo, float hi) {
    unsigned long long r;
    asm("mov.b64 %0, {%1, %2};" : "=l"(r) : "f"(lo), "f"(hi));
    return r;
}
__device__ __forceinline__ unsigned long long bcast2(float v) {
    unsigned long long r;
    asm("mov.b64 %0, {%1, %1};" : "=l"(r) : "f"(v));
    return r;
}
__device__ __forceinline__ void unpack2(unsigned long long v, float& lo, float& hi) {
    asm("mov.b64 {%0, %1}, %2;" : "=f"(lo), "=f"(hi) : "l"(v));
}
__device__ __forceinline__ void fma2(unsigned long long& acc, unsigned long long a,
                                     unsigned long long b) {
    asm("fma.rn.f32x2 %0, %1, %2, %0;" : "+l"(acc) : "l"(a), "l"(b));
}
__device__ __forceinline__ unsigned long long add2(unsigned long long a, unsigned long long b) {
    unsigned long long r;
    asm("add.rn.f32x2 %0, %1, %2;" : "=l"(r) : "l"(a), "l"(b));
    return r;
}

// ---------------- shared micro-kernel ----------------
// 8 rows (fixed per warp -> smem broadcast a-loads) x 4 cols (lane*4) x K=128.
// acc[r][0] = packed cols (c0,c0+1), acc[r][1] = packed cols (c0+2,c0+3).
__device__ __forceinline__ void gemm8x4(const float* __restrict__ sA,  // rows base, stride 128
                                        const float* __restrict__ sW,  // [128][128]
                                        int lane, unsigned long long acc[8][2]) {
    const float* wbase = sW + lane * 4;
#pragma unroll 2
    for (int k = 0; k < 128; k += 4) {
        float4 a4[8];
#pragma unroll
        for (int r = 0; r < 8; r++)
            a4[r] = *reinterpret_cast<const float4*>(sA + r * 128 + k);
#pragma unroll
        for (int kk = 0; kk < 4; kk++) {
            ulonglong2 w = *reinterpret_cast<const ulonglong2*>(wbase + (k + kk) * 128);
#pragma unroll
            for (int r = 0; r < 8; r++) {
                float a = (kk == 0) ? a4[r].x : (kk == 1) ? a4[r].y : (kk == 2) ? a4[r].z : a4[r].w;
                unsigned long long a2 = bcast2(a);
                fma2(acc[r][0], a2, w.x);
                fma2(acc[r][1], a2, w.y);
            }
        }
    }
}

// ---------------- Kernel A: node precompute ----------------
// P = x @ [W1a | W1b], b1 folded into first 512 columns.
// Block: 64 nodes x 128 output cols, K = 128 (full depth, single stage).
#define A_SMEM_FLOATS (64 * 128 + 128 * 128)
__global__ __launch_bounds__(256, 1) void node_kernel(const float* __restrict__ x,
                                                      const float* __restrict__ W1,
                                                      const float* __restrict__ b1) {
    extern __shared__ float sm[];
    float* sX = sm;              // [64][128]
    float* sW = sm + 64 * 128;   // [128][128]

    const int n0 = blockIdx.x * 64;
    const int c0 = blockIdx.y * 128;   // over 1024 combined cols
    const int tid = threadIdx.x, warp = tid >> 5, lane = tid & 31;

    // stage x tile
#pragma unroll
    for (int i = 0; i < 8; i++) {
        int idx = tid + i * 256;           // 2048 float4
        int r = idx >> 5, c4 = (idx & 31) * 4;
        int n = n0 + r;
        float4 v = make_float4(0.f, 0.f, 0.f, 0.f);
        if (n < NN) v = *reinterpret_cast<const float4*>(x + (size_t)n * DN + c4);
        *reinterpret_cast<float4*>(sX + r * 128 + c4) = v;
    }
    // stage W tile: cols<512 from W1 rows [0,128), cols>=512 from rows [128,256)
    const int krow0 = (c0 < 512) ? 0 : 128;
    const int wc0 = (c0 < 512) ? c0 : (c0 - 512);
#pragma unroll
    for (int i = 0; i < 16; i++) {
        int idx = tid + i * 256;           // 4096 float4
        int k = idx >> 5, j4 = (idx & 31) * 4;
        *reinterpret_cast<float4*>(sW + k * 128 + j4) =
            *reinterpret_cast<const float4*>(W1 + (size_t)(krow0 + k) * DH + wc0 + j4);
    }
    __syncthreads();

    unsigned long long acc[8][2];
    unsigned long long i0 = 0ull, i1 = 0ull;
    if (c0 < 512) {   // fold b1 into Pa half
        float4 b = *reinterpret_cast<const float4*>(b1 + c0 + lane * 4);
        i0 = pack2(b.x, b.y);
        i1 = pack2(b.z, b.w);
    }
#pragma unroll
    for (int r = 0; r < 8; r++) { acc[r][0] = i0; acc[r][1] = i1; }

    gemm8x4(sX + warp * 8 * 128, sW, lane, acc);

    const int r0 = warp * 8;
#pragma unroll
    for (int r = 0; r < 8; r++) {
        int n = n0 + r0 + r;
        if (n < NN) {
            float f0, f1, f2, f3;
            unpack2(acc[r][0], f0, f1);
            unpack2(acc[r][1], f2, f3);
            *reinterpret_cast<float4*>(g_P + (size_t)n * 1024 + c0 + lane * 4) =
                make_float4(f0, f1, f2, f3);
        }
    }
}

// ---------------- Kernel B: fused edge MLP ----------------
// Block = 64 edges, 256 threads. Hidden dim in 4 chunks of 128.
// Per chunk: H = relu(P_a[row] + P_b[col] + EA @ W1c_chunk)  -> sH
//            Yacc += sH @ W2_chunk  (Yacc persistent in registers)
// Register diet vs R9-passing version: keep 8+8 int node indices (16 regs)
// instead of 8+8 hoisted 64-bit pointers (32 regs); recompute addresses per chunk.
#define B_SMEM_BYTES ((64 * 128 + 128 * 128 + 64 * 128 + 128 * 128) * 4 + 128 * 4)
__global__ __launch_bounds__(256, 1) void edge_kernel(const float* __restrict__ ea,
                                                      const int* __restrict__ eidx,
                                                      const float* __restrict__ W1,
                                                      const float* __restrict__ W2,
                                                      const float* __restrict__ b2,
                                                      float* __restrict__ out) {
    extern __shared__ float sm[];
    float* sEA = sm;                       // [64][128]
    float* sW1 = sm + 8192;                // [128][128]  (W1c chunk)
    float* sH  = sm + 8192 + 16384;        // [64][128]
    float* sW2 = sm + 8192 + 16384 + 8192; // [128][128]  (W2 chunk)
    int* sIdx = (int*)(sm + 49152);        // [0:64) row idx, [64:128) col idx

    const int e0 = blockIdx.x * 64;
    const int tid = threadIdx.x, warp = tid >> 5, lane = tid & 31;

    if (tid < 128) {
        int e = e0 + (tid & 63);
        int which = tid >> 6;              // 0 = row (source), 1 = col (target)
        int v = 0;
        if (e < NE) v = eidx[(size_t)which * NE + e];
        sIdx[tid] = v;
    }
    // stage edge_attr tile
#pragma unroll
    for (int i = 0; i < 8; i++) {
        int idx = tid + i * 256;
        int r = idx >> 5, c4 = (idx & 31) * 4;
        int e = e0 + r;
        float4 v = make_float4(0.f, 0.f, 0.f, 0.f);
        if (e < NE) v = *reinterpret_cast<const float4*>(ea + (size_t)e * DE + c4);
        *reinterpret_cast<float4*>(sEA + r * 128 + c4) = v;
    }
    __syncthreads();

    // persistent output accumulators: 8 edges x 4 out-cols, init with b2
    unsigned long long yacc[8][2];
    {
        float4 b = *reinterpret_cast<const float4*>(b2 + lane * 4);
        unsigned long long i0 = pack2(b.x, b.y), i1 = pack2(b.z, b.w);
#pragma unroll
        for (int r = 0; r < 8; r++) { yacc[r][0] = i0; yacc[r][1] = i1; }
    }
    const int r0 = warp * 8;

    // node indices for this warp's 8 edges (16 int regs, cheaper than pointers)
    int ia[8], ib[8];
#pragma unroll
    for (int r = 0; r < 8; r++) {
        ia[r] = sIdx[r0 + r];
        ib[r] = sIdx[64 + r0 + r];
    }

    for (int c = 0; c < 4; c++) {
        if (c > 0) __syncthreads();   // prior phase-d must drain before restaging

        // stage W1c chunk (W1 rows 256..383, col block c) and W2 chunk (row block c)
#pragma unroll
        for (int i = 0; i < 16; i++) {
            int idx = tid + i * 256;
            int k = idx >> 5, j4 = (idx & 31) * 4;
            *reinterpret_cast<float4*>(sW1 + k * 128 + j4) =
                *reinterpret_cast<const float4*>(W1 + (size_t)(256 + k) * DH + c * 128 + j4);
            *reinterpret_cast<float4*>(sW2 + k * 128 + j4) =
                *reinterpret_cast<const float4*>(W2 + (size_t)(c * 128 + k) * DO + j4);
        }

        // gather precomputed node terms (global; latency overlapped with staging)
        unsigned long long hacc[8][2];
        const int coff = c * 128 + lane * 4;
#pragma unroll
        for (int r = 0; r < 8; r++) {
            ulonglong2 va = *reinterpret_cast<const ulonglong2*>(
                g_P + (size_t)ia[r] * 1024 + coff);
            ulonglong2 vb = *reinterpret_cast<const ulonglong2*>(
                g_P + (size_t)ib[r] * 1024 + 512 + coff);
            hacc[r][0] = add2(va.x, vb.x);   // b1 already folded into Pa
            hacc[r][1] = add2(va.y, vb.y);
        }
        __syncthreads();

        // hacc += EA @ W1c_chunk
        gemm8x4(sEA + r0 * 128, sW1, lane, hacc);

        // relu -> sH
#pragma unroll
        for (int r = 0; r < 8; r++) {
            float f0, f1, f2, f3;
            unpack2(hacc[r][0], f0, f1);
            unpack2(hacc[r][1], f2, f3);
            f0 = fmaxf(f0, 0.f); f1 = fmaxf(f1, 0.f);
            f2 = fmaxf(f2, 0.f); f3 = fmaxf(f3, 0.f);
            *reinterpret_cast<float4*>(sH + (r0 + r) * 128 + lane * 4) =
                make_float4(f0, f1, f2, f3);
        }
        __syncthreads();

        // yacc += sH @ W2_chunk
        gemm8x4(sH + r0 * 128, sW2, lane, yacc);
    }

    // write output
#pragma unroll
    for (int r = 0; r < 8; r++) {
        int e = e0 + r0 + r;
        if (e < NE) {
            float f0, f1, f2, f3;
            unpack2(yacc[r][0], f0, f1);
            unpack2(yacc[r][1], f2, f3);
            *reinterpret_cast<float4*>(out + (size_t)e * DO + lane * 4) =
                make_float4(f0, f1, f2, f3);
        }
    }
}

extern "C" void kernel_launch(void* const* d_in, const int* in_sizes, int n_in,
                              void* d_out, int out_size) {
    const float* x    = (const float*)d_in[0];
    const int*   eidx = (const int*)d_in[1];
    const float* ea   = (const float*)d_in[2];
    const float* W1   = (const float*)d_in[3];
    const float* b1   = (const float*)d_in[4];
    const float* W2   = (const float*)d_in[5];
    const float* b2   = (const float*)d_in[6];
    float* out = (float*)d_out;

    const int a_smem = A_SMEM_FLOATS * 4;          // 96 KB
    const int b_smem = B_SMEM_BYTES;               // ~192.5 KB

    static bool attr_done = false;                 // host-side; idempotent driver setup
    if (!attr_done) {
        cudaFuncSetAttribute(node_kernel, cudaFuncAttributeMaxDynamicSharedMemorySize, a_smem);
        cudaFuncSetAttribute(edge_kernel, cudaFuncAttributeMaxDynamicSharedMemorySize, b_smem);
        cudaFuncSetAttribute(node_kernel, cudaFuncAttributePreferredSharedMemoryCarveout,
                             cudaSharedmemCarveoutMaxShared);
        cudaFuncSetAttribute(edge_kernel, cudaFuncAttributePreferredSharedMemoryCarveout,
                             cudaSharedmemCarveoutMaxShared);
        attr_done = true;
    }

    dim3 gridA((NN + 63) / 64, 1024 / 128);        // 782 x 8
    node_kernel<<<gridA, 256, a_smem>>>(x, W1, b1);

    int gridB = (NE + 63) / 64;                    // 7813
    edge_kernel<<<gridB, 256, b_smem>>>(ea, eidx, W1, W2, b2, out);
}

// round 14
// speedup vs baseline: 1.0462x; 1.0207x over previous
#include <cuda_runtime.h>
#include <cstdint>

// Problem constants
#define NN 50000      // nodes
#define NE 500000     // edges
#define DN 128        // node feat
#define DE 128        // edge feat
#define DH 512        // hidden
#define DO 128        // out

// Scratch: P[node][0:512]   = x @ W1[0:128,:]   + b1
//          P[node][512:1024] = x @ W1[128:256,:]
__device__ float g_P[(size_t)NN * 1024];

// ---------------- packed fp32x2 helpers (PTX ISA 8.7, sm_100+) ----------------
__device__ __forceinline__ unsigned long long pack2(float lo, float hi) {
    unsigned long long r;
    asm("mov.b64 %0, {%1, %2};" : "=l"(r) : "f"(lo), "f"(hi));
    return r;
}
__device__ __forceinline__ unsigned long long bcast2(float v) {
    unsigned long long r;
    asm("mov.b64 %0, {%1, %1};" : "=l"(r) : "f"(v));
    return r;
}
__device__ __forceinline__ void unpack2(unsigned long long v, float& lo, float& hi) {
    asm("mov.b64 {%0, %1}, %2;" : "=f"(lo), "=f"(hi) : "l"(v));
}
__device__ __forceinline__ void fma2(unsigned long long& acc, unsigned long long a,
                                     unsigned long long b) {
    asm("fma.rn.f32x2 %0, %1, %2, %0;" : "+l"(acc) : "l"(a), "l"(b));
}
__device__ __forceinline__ unsigned long long add2(unsigned long long a, unsigned long long b) {
    unsigned long long r;
    asm("add.rn.f32x2 %0, %1, %2;" : "=l"(r) : "l"(a), "l"(b));
    return r;
}

// ---------------- shared micro-kernel, K=64 slice ----------------
// 8 rows (fixed per warp -> smem broadcast a-loads) x 4 cols (lane*4) x K=64.
// sW is a [64][128] K-half weight tile.
__device__ __forceinline__ void gemm8x4_k64(const float* __restrict__ sA,  // rows, stride 128
                                            const float* __restrict__ sW,  // [64][128]
                                            int lane, unsigned long long acc[8][2]) {
    const float* wbase = sW + lane * 4;
#pragma unroll 2
    for (int k = 0; k < 64; k += 4) {
        float4 a4[8];
#pragma unroll
        for (int r = 0; r < 8; r++)
            a4[r] = *reinterpret_cast<const float4*>(sA + r * 128 + k);
#pragma unroll
        for (int kk = 0; kk < 4; kk++) {
            ulonglong2 w = *reinterpret_cast<const ulonglong2*>(wbase + (k + kk) * 128);
#pragma unroll
            for (int r = 0; r < 8; r++) {
                float a = (kk == 0) ? a4[r].x : (kk == 1) ? a4[r].y : (kk == 2) ? a4[r].z : a4[r].w;
                unsigned long long a2 = bcast2(a);
                fma2(acc[r][0], a2, w.x);
                fma2(acc[r][1], a2, w.y);
            }
        }
    }
}

// Full K=128 variant for the node kernel (sW is [128][128]).
__device__ __forceinline__ void gemm8x4(const float* __restrict__ sA,
                                        const float* __restrict__ sW,
                                        int lane, unsigned long long acc[8][2]) {
    gemm8x4_k64(sA, sW, lane, acc);
    gemm8x4_k64(sA + 64, sW + 64 * 128, lane, acc);
}

// ---------------- Kernel A: node precompute ----------------
// P = x @ [W1a | W1b], b1 folded into first 512 columns.
// Block: 64 nodes x 128 output cols, K = 128. 96KB smem -> 2 CTAs/SM.
#define A_SMEM_FLOATS (64 * 128 + 128 * 128)
__global__ __launch_bounds__(256, 2) void node_kernel(const float* __restrict__ x,
                                                      const float* __restrict__ W1,
                                                      const float* __restrict__ b1) {
    extern __shared__ float sm[];
    float* sX = sm;              // [64][128]
    float* sW = sm + 64 * 128;   // [128][128]

    const int n0 = blockIdx.x * 64;
    const int c0 = blockIdx.y * 128;   // over 1024 combined cols
    const int tid = threadIdx.x, warp = tid >> 5, lane = tid & 31;

    // stage x tile
#pragma unroll
    for (int i = 0; i < 8; i++) {
        int idx = tid + i * 256;           // 2048 float4
        int r = idx >> 5, c4 = (idx & 31) * 4;
        int n = n0 + r;
        float4 v = make_float4(0.f, 0.f, 0.f, 0.f);
        if (n < NN) v = *reinterpret_cast<const float4*>(x + (size_t)n * DN + c4);
        *reinterpret_cast<float4*>(sX + r * 128 + c4) = v;
    }
    // stage W tile: cols<512 from W1 rows [0,128), cols>=512 from rows [128,256)
    const int krow0 = (c0 < 512) ? 0 : 128;
    const int wc0 = (c0 < 512) ? c0 : (c0 - 512);
#pragma unroll
    for (int i = 0; i < 16; i++) {
        int idx = tid + i * 256;           // 4096 float4
        int k = idx >> 5, j4 = (idx & 31) * 4;
        *reinterpret_cast<float4*>(sW + k * 128 + j4) =
            *reinterpret_cast<const float4*>(W1 + (size_t)(krow0 + k) * DH + wc0 + j4);
    }
    __syncthreads();

    unsigned long long acc[8][2];
    unsigned long long i0 = 0ull, i1 = 0ull;
    if (c0 < 512) {   // fold b1 into Pa half
        float4 b = *reinterpret_cast<const float4*>(b1 + c0 + lane * 4);
        i0 = pack2(b.x, b.y);
        i1 = pack2(b.z, b.w);
    }
#pragma unroll
    for (int r = 0; r < 8; r++) { acc[r][0] = i0; acc[r][1] = i1; }

    gemm8x4(sX + warp * 8 * 128, sW, lane, acc);

    const int r0 = warp * 8;
#pragma unroll
    for (int r = 0; r < 8; r++) {
        int n = n0 + r0 + r;
        if (n < NN) {
            float f0, f1, f2, f3;
            unpack2(acc[r][0], f0, f1);
            unpack2(acc[r][1], f2, f3);
            *reinterpret_cast<float4*>(g_P + (size_t)n * 1024 + c0 + lane * 4) =
                make_float4(f0, f1, f2, f3);
        }
    }
}

// ---------------- Kernel B: fused edge MLP (2 CTAs/SM) ----------------
// Block = 64 edges, 256 threads. Hidden dim in 4 chunks of 128; weights
// staged through a single 32KB K-half buffer (96.5KB smem total) so that
// two CTAs co-reside per SM. __launch_bounds__(256,2) caps regs at 128.
#define B_SMEM_FLOATS (3 * 64 * 128)               // sEA + sW + sH
#define B_SMEM_BYTES (B_SMEM_FLOATS * 4 + 128 * 4) // + sIdx
__global__ __launch_bounds__(256, 2) void edge_kernel(const float* __restrict__ ea,
                                                      const int* __restrict__ eidx,
                                                      const float* __restrict__ W1,
                                                      const float* __restrict__ W2,
                                                      const float* __restrict__ b2,
                                                      float* __restrict__ out) {
    extern __shared__ float sm[];
    float* sEA = sm;                 // [64][128]
    float* sW  = sm + 8192;          // [64][128]  single K-half weight buffer
    float* sH  = sm + 16384;         // [64][128]
    int* sIdx  = (int*)(sm + 24576); // [0:64) row idx, [64:128) col idx

    const int e0 = blockIdx.x * 64;
    const int tid = threadIdx.x, warp = tid >> 5, lane = tid & 31;

    if (tid < 128) {
        int e = e0 + (tid & 63);
        int which = tid >> 6;              // 0 = row (source), 1 = col (target)
        int v = 0;
        if (e < NE) v = eidx[(size_t)which * NE + e];
        sIdx[tid] = v;
    }
    // stage edge_attr tile
#pragma unroll
    for (int i = 0; i < 8; i++) {
        int idx = tid + i * 256;
        int r = idx >> 5, c4 = (idx & 31) * 4;
        int e = e0 + r;
        float4 v = make_float4(0.f, 0.f, 0.f, 0.f);
        if (e < NE) v = *reinterpret_cast<const float4*>(ea + (size_t)e * DE + c4);
        *reinterpret_cast<float4*>(sEA + r * 128 + c4) = v;
    }
    __syncthreads();

    // persistent output accumulators: 8 edges x 4 out-cols, init with b2
    unsigned long long yacc[8][2];
    {
        float4 b = *reinterpret_cast<const float4*>(b2 + lane * 4);
        unsigned long long i0 = pack2(b.x, b.y), i1 = pack2(b.z, b.w);
#pragma unroll
        for (int r = 0; r < 8; r++) { yacc[r][0] = i0; yacc[r][1] = i1; }
    }
    const int r0 = warp * 8;

    // node indices for this warp's 8 edges
    int ia[8], ib[8];
#pragma unroll
    for (int r = 0; r < 8; r++) {
        ia[r] = sIdx[r0 + r];
        ib[r] = sIdx[64 + r0 + r];
    }

    for (int c = 0; c < 4; c++) {
        // gathers: issue early, overlap with first weight staging
        unsigned long long hacc[8][2];
        const int coff = c * 128 + lane * 4;
#pragma unroll
        for (int r = 0; r < 8; r++) {
            ulonglong2 va = *reinterpret_cast<const ulonglong2*>(
                g_P + (size_t)ia[r] * 1024 + coff);
            ulonglong2 vb = *reinterpret_cast<const ulonglong2*>(
                g_P + (size_t)ib[r] * 1024 + 512 + coff);
            hacc[r][0] = add2(va.x, vb.x);   // b1 already folded into Pa
            hacc[r][1] = add2(va.y, vb.y);
        }

        // ---- W1c K-half 0: W1 rows [256, 320), cols c*128.. ----
        __syncthreads();   // prior readers of sW done
#pragma unroll
        for (int i = 0; i < 8; i++) {
            int idx = tid + i * 256;                 // 2048 float4
            int k = idx >> 5, j4 = (idx & 31) * 4;
            *reinterpret_cast<float4*>(sW + k * 128 + j4) =
                *reinterpret_cast<const float4*>(W1 + (size_t)(256 + k) * DH + c * 128 + j4);
        }
        __syncthreads();
        gemm8x4_k64(sEA + r0 * 128, sW, lane, hacc);

        // ---- W1c K-half 1: W1 rows [320, 384) ----
        __syncthreads();
#pragma unroll
        for (int i = 0; i < 8; i++) {
            int idx = tid + i * 256;
            int k = idx >> 5, j4 = (idx & 31) * 4;
            *reinterpret_cast<float4*>(sW + k * 128 + j4) =
                *reinterpret_cast<const float4*>(W1 + (size_t)(320 + k) * DH + c * 128 + j4);
        }
        __syncthreads();
        gemm8x4_k64(sEA + r0 * 128 + 64, sW, lane, hacc);

        // relu -> sH (each warp writes/reads only its own 8 rows)
#pragma unroll
        for (int r = 0; r < 8; r++) {
            float f0, f1, f2, f3;
            unpack2(hacc[r][0], f0, f1);
            unpack2(hacc[r][1], f2, f3);
            f0 = fmaxf(f0, 0.f); f1 = fmaxf(f1, 0.f);
            f2 = fmaxf(f2, 0.f); f3 = fmaxf(f3, 0.f);
            *reinterpret_cast<float4*>(sH + (r0 + r) * 128 + lane * 4) =
                make_float4(f0, f1, f2, f3);
        }

        // ---- W2 K-half 0: W2 rows [c*128, c*128+64) ----
        __syncthreads();
#pragma unroll
        for (int i = 0; i < 8; i++) {
            int idx = tid + i * 256;
            int k = idx >> 5, j4 = (idx & 31) * 4;
            *reinterpret_cast<float4*>(sW + k * 128 + j4) =
                *reinterpret_cast<const float4*>(W2 + (size_t)(c * 128 + k) * DO + j4);
        }
        __syncthreads();
        gemm8x4_k64(sH + r0 * 128, sW, lane, yacc);

        // ---- W2 K-half 1: W2 rows [c*128+64, c*128+128) ----
        __syncthreads();
#pragma unroll
        for (int i = 0; i < 8; i++) {
            int idx = tid + i * 256;
            int k = idx >> 5, j4 = (idx & 31) * 4;
            *reinterpret_cast<float4*>(sW + k * 128 + j4) =
                *reinterpret_cast<const float4*>(W2 + (size_t)(c * 128 + 64 + k) * DO + j4);
        }
        __syncthreads();
        gemm8x4_k64(sH + r0 * 128 + 64, sW, lane, yacc);
    }

    // write output
#pragma unroll
    for (int r = 0; r < 8; r++) {
        int e = e0 + r0 + r;
        if (e < NE) {
            float f0, f1, f2, f3;
            unpack2(yacc[r][0], f0, f1);
            unpack2(yacc[r][1], f2, f3);
            *reinterpret_cast<float4*>(out + (size_t)e * DO + lane * 4) =
                make_float4(f0, f1, f2, f3);
        }
    }
}

extern "C" void kernel_launch(void* const* d_in, const int* in_sizes, int n_in,
                              void* d_out, int out_size) {
    const float* x    = (const float*)d_in[0];
    const int*   eidx = (const int*)d_in[1];
    const float* ea   = (const float*)d_in[2];
    const float* W1   = (const float*)d_in[3];
    const float* b1   = (const float*)d_in[4];
    const float* W2   = (const float*)d_in[5];
    const float* b2   = (const float*)d_in[6];
    float* out = (float*)d_out;

    const int a_smem = A_SMEM_FLOATS * 4;          // 96 KB
    const int b_smem = B_SMEM_BYTES;               // 96.5 KB -> 2 CTAs/SM

    static bool attr_done = false;                 // host-side; idempotent driver setup
    if (!attr_done) {
        cudaFuncSetAttribute(node_kernel, cudaFuncAttributeMaxDynamicSharedMemorySize, a_smem);
        cudaFuncSetAttribute(edge_kernel, cudaFuncAttributeMaxDynamicSharedMemorySize, b_smem);
        cudaFuncSetAttribute(node_kernel, cudaFuncAttributePreferredSharedMemoryCarveout,
                             cudaSharedmemCarveoutMaxShared);
        cudaFuncSetAttribute(edge_kernel, cudaFuncAttributePreferredSharedMemoryCarveout,
                             cudaSharedmemCarveoutMaxShared);
        attr_done = true;
    }

    dim3 gridA((NN + 63) / 64, 1024 / 128);        // 782 x 8
    node_kernel<<<gridA, 256, a_smem>>>(x, W1, b1);

    int gridB = (NE + 63) / 64;                    // 7813
    edge_kernel<<<gridB, 256, b_smem>>>(ea, eidx, W1, W2, b2, out);
}